// round 10
// baseline (speedup 1.0000x reference)
#include <cuda_runtime.h>
#include <cuda_fp16.h>
#include <cstdint>

// Problem dims (fixed by the dataset)
#define S_DIM 2048
#define B_DIM 2
#define E_DIM 1024
#define H_DIM 16
#define D_DIM 64
#define T_DIM 2048
#define M_DIM (S_DIM * B_DIM)          // 4096 rows of the flattened (s,b) axis
#define BHT   (B_DIM * H_DIM * T_DIM)  // 65536: stride of s in the scores tensor

// -------- static scratch (allocation-free rule: __device__ globals) --------
__device__ float  g_q[M_DIM * E_DIM];                         // 16 MB
__device__ float  g_k[M_DIM * E_DIM];                         // 16 MB
__device__ float  g_v[M_DIM * E_DIM];                         // 16 MB
__device__ float  g_o[M_DIM * E_DIM];                         // 16 MB
__device__ __half g_p[(size_t)S_DIM * B_DIM * H_DIM * T_DIM]; // 256 MiB: exp(scores), fp16
__device__ float  g_rd[S_DIM * B_DIM * T_DIM];                // 32 MB: 1/sum_h

// ---------------- mma wrappers ----------------
__device__ __forceinline__ uint32_t f2tf32(float x) {
    uint32_t r;
    asm("cvt.rna.tf32.f32 %0, %1;" : "=r"(r) : "f"(x));
    return r;
}
__device__ __forceinline__ float tf32f(float x) {
    return __uint_as_float(f2tf32(x));
}

__device__ __forceinline__
void mma_tf32_16x8x8(float c[4], const uint32_t a[4], uint32_t b0, uint32_t b1) {
    asm volatile(
        "mma.sync.aligned.m16n8k8.row.col.f32.tf32.tf32.f32 "
        "{%0,%1,%2,%3}, {%4,%5,%6,%7}, {%8,%9}, {%0,%1,%2,%3};"
        : "+f"(c[0]), "+f"(c[1]), "+f"(c[2]), "+f"(c[3])
        : "r"(a[0]), "r"(a[1]), "r"(a[2]), "r"(a[3]), "r"(b0), "r"(b1));
}

__device__ __forceinline__
void mma_f16_16x8x16(float c[4], const uint32_t a[4], uint32_t b0, uint32_t b1) {
    asm volatile(
        "mma.sync.aligned.m16n8k16.row.col.f32.f16.f16.f32 "
        "{%0,%1,%2,%3}, {%4,%5,%6,%7}, {%8,%9}, {%0,%1,%2,%3};"
        : "+f"(c[0]), "+f"(c[1]), "+f"(c[2]), "+f"(c[3])
        : "r"(a[0]), "r"(a[1]), "r"(a[2]), "r"(a[3]), "r"(b0), "r"(b1));
}

// ===========================================================================
// Split-TF32 (3-mma) NT GEMM tile: C[128 x 64] = A * W^T + bias, K = 1024.
// A: M x 1024 row-major, W: N x 1024 row-major. hi/lo decomposition gives
// fp32-grade accuracy on the tensor pipe. 8 warps as 4(m) x 2(n); warp tile
// 32x32 = (2 m16) x (4 n8); BK=16 with register-prefetch double buffering.
// ===========================================================================
__device__ __forceinline__
void gemm_nt_tf32x3_tile(const float* __restrict__ A,
                         const float* __restrict__ W,
                         const float* __restrict__ bias,
                         float* __restrict__ C,
                         int bm, int bn)
{
    __shared__ float Ahi[128][20];
    __shared__ float Alo[128][20];
    __shared__ float Bhi[64][20];
    __shared__ float Blo[64][20];

    const int tid  = threadIdx.x;
    const int wid  = tid >> 5;
    const int lane = tid & 31;
    const int wm = wid >> 1;         // 0..3
    const int wn = wid & 1;          // 0..1
    const int g   = lane >> 2;       // 0..7
    const int tig = lane & 3;        // 0..3

    const int a_row0 = tid >> 2;         // 0..63
    const int a_row1 = 64 + a_row0;      // 64..127
    const int c4     = (tid & 3) * 4;    // 0,4,8,12

    float acc[2][4][4];
#pragma unroll
    for (int mi = 0; mi < 2; ++mi)
#pragma unroll
        for (int ni = 0; ni < 4; ++ni)
#pragma unroll
            for (int r = 0; r < 4; ++r) acc[mi][ni][r] = 0.f;

    float4 pa0 = *(const float4*)&A[(size_t)(bm + a_row0) * 1024 + c4];
    float4 pa1 = *(const float4*)&A[(size_t)(bm + a_row1) * 1024 + c4];
    float4 pw  = *(const float4*)&W[(size_t)(bn + a_row0) * 1024 + c4];

    for (int kt = 0; kt < 1024; kt += 16) {
        // hi/lo split + store to smem
        {
            float h;
            h = tf32f(pa0.x); Ahi[a_row0][c4+0] = h; Alo[a_row0][c4+0] = tf32f(pa0.x - h);
            h = tf32f(pa0.y); Ahi[a_row0][c4+1] = h; Alo[a_row0][c4+1] = tf32f(pa0.y - h);
            h = tf32f(pa0.z); Ahi[a_row0][c4+2] = h; Alo[a_row0][c4+2] = tf32f(pa0.z - h);
            h = tf32f(pa0.w); Ahi[a_row0][c4+3] = h; Alo[a_row0][c4+3] = tf32f(pa0.w - h);
            h = tf32f(pa1.x); Ahi[a_row1][c4+0] = h; Alo[a_row1][c4+0] = tf32f(pa1.x - h);
            h = tf32f(pa1.y); Ahi[a_row1][c4+1] = h; Alo[a_row1][c4+1] = tf32f(pa1.y - h);
            h = tf32f(pa1.z); Ahi[a_row1][c4+2] = h; Alo[a_row1][c4+2] = tf32f(pa1.z - h);
            h = tf32f(pa1.w); Ahi[a_row1][c4+3] = h; Alo[a_row1][c4+3] = tf32f(pa1.w - h);
            h = tf32f(pw.x);  Bhi[a_row0][c4+0] = h; Blo[a_row0][c4+0] = tf32f(pw.x - h);
            h = tf32f(pw.y);  Bhi[a_row0][c4+1] = h; Blo[a_row0][c4+1] = tf32f(pw.y - h);
            h = tf32f(pw.z);  Bhi[a_row0][c4+2] = h; Blo[a_row0][c4+2] = tf32f(pw.z - h);
            h = tf32f(pw.w);  Bhi[a_row0][c4+3] = h; Blo[a_row0][c4+3] = tf32f(pw.w - h);
        }
        __syncthreads();

        if (kt + 16 < 1024) {
            int kn = kt + 16;
            pa0 = *(const float4*)&A[(size_t)(bm + a_row0) * 1024 + kn + c4];
            pa1 = *(const float4*)&A[(size_t)(bm + a_row1) * 1024 + kn + c4];
            pw  = *(const float4*)&W[(size_t)(bn + a_row0) * 1024 + kn + c4];
        }

#pragma unroll
        for (int ks = 0; ks < 2; ++ks) {
            int k8 = ks * 8;
            uint32_t ah[2][4], al[2][4];
#pragma unroll
            for (int mi = 0; mi < 2; ++mi) {
                int r = wm * 32 + mi * 16 + g;
                ah[mi][0] = __float_as_uint(Ahi[r][k8 + tig]);
                ah[mi][1] = __float_as_uint(Ahi[r + 8][k8 + tig]);
                ah[mi][2] = __float_as_uint(Ahi[r][k8 + tig + 4]);
                ah[mi][3] = __float_as_uint(Ahi[r + 8][k8 + tig + 4]);
                al[mi][0] = __float_as_uint(Alo[r][k8 + tig]);
                al[mi][1] = __float_as_uint(Alo[r + 8][k8 + tig]);
                al[mi][2] = __float_as_uint(Alo[r][k8 + tig + 4]);
                al[mi][3] = __float_as_uint(Alo[r + 8][k8 + tig + 4]);
            }
#pragma unroll
            for (int ni = 0; ni < 4; ++ni) {
                int c = wn * 32 + ni * 8 + g;
                uint32_t bh0 = __float_as_uint(Bhi[c][k8 + tig]);
                uint32_t bh1 = __float_as_uint(Bhi[c][k8 + tig + 4]);
                uint32_t bl0 = __float_as_uint(Blo[c][k8 + tig]);
                uint32_t bl1 = __float_as_uint(Blo[c][k8 + tig + 4]);
#pragma unroll
                for (int mi = 0; mi < 2; ++mi) {
                    mma_tf32_16x8x8(acc[mi][ni], ah[mi], bh0, bh1);
                    mma_tf32_16x8x8(acc[mi][ni], ah[mi], bl0, bl1);
                    mma_tf32_16x8x8(acc[mi][ni], al[mi], bh0, bh1);
                }
            }
        }
        __syncthreads();
    }

#pragma unroll
    for (int mi = 0; mi < 2; ++mi) {
#pragma unroll
        for (int ni = 0; ni < 4; ++ni) {
            int row = bm + wm * 32 + mi * 16 + g;
            int col = bn + wn * 32 + ni * 8 + 2 * tig;
            float2 bs = *(const float2*)&bias[col];
            float2 o0 = {acc[mi][ni][0] + bs.x, acc[mi][ni][1] + bs.y};
            float2 o1 = {acc[mi][ni][2] + bs.x, acc[mi][ni][3] + bs.y};
            *(float2*)&C[(size_t)row * 1024 + col]       = o0;
            *(float2*)&C[(size_t)(row + 8) * 1024 + col] = o1;
        }
    }
}

// Kernel 1/5: fused Q/K/V projections (blockIdx.z selects the triple)
__global__ __launch_bounds__(256)
void qkv_proj_kernel(const float* __restrict__ x,
                     const float* __restrict__ Wq, const float* __restrict__ bq,
                     const float* __restrict__ Wk, const float* __restrict__ bk,
                     const float* __restrict__ Wv, const float* __restrict__ bv,
                     float* __restrict__ q, float* __restrict__ k,
                     float* __restrict__ v)
{
    const float* W; const float* bias; float* C;
    if (blockIdx.z == 0)      { W = Wq; bias = bq; C = q; }
    else if (blockIdx.z == 1) { W = Wk; bias = bk; C = k; }
    else                      { W = Wv; bias = bv; C = v; }
    gemm_nt_tf32x3_tile(x, W, bias, C, blockIdx.y * 128, blockIdx.x * 64);
}

// Kernel 5/5: output projection
__global__ __launch_bounds__(256)
void out_proj_kernel(const float* __restrict__ o,
                     const float* __restrict__ Wo, const float* __restrict__ bo,
                     float* __restrict__ out)
{
    gemm_nt_tf32x3_tile(o, Wo, bo, out, blockIdx.y * 128, blockIdx.x * 64);
}

// ===========================================================================
// Kernel 2/5: p[s,b,h,t] = exp((q.k)/8) via tf32 mma.m16n8k8 (unchanged).
// ===========================================================================
__global__ __launch_bounds__(256)
void scores_mma_kernel(const float* __restrict__ Q,
                       const float* __restrict__ Kv,
                       __half* __restrict__ P)
{
    __shared__ float Qs[128][36];
    __shared__ float Ks[64][36];

    const int bh = blockIdx.z;
    const int b  = bh / H_DIM;
    const int h  = bh % H_DIM;
    const float* Aq = Q  + (size_t)b * E_DIM + h * D_DIM;
    const float* Ak = Kv + (size_t)b * E_DIM + h * D_DIM;
    __half* Pc = P + (size_t)bh * T_DIM;

    const int bm = blockIdx.y * 128;
    const int bn = blockIdx.x * 64;
    const int tid  = threadIdx.x;
    const int wid  = tid >> 5;
    const int lane = tid & 31;
    const int wm = wid >> 1;
    const int wn = wid & 1;
    const int g   = lane >> 2;
    const int tig = lane & 3;

    float acc[2][4][4];
#pragma unroll
    for (int mi = 0; mi < 2; ++mi)
#pragma unroll
        for (int ni = 0; ni < 4; ++ni)
#pragma unroll
            for (int r = 0; r < 4; ++r) acc[mi][ni][r] = 0.f;

#pragma unroll
    for (int kc = 0; kc < D_DIM; kc += 32) {
#pragma unroll
        for (int i = 0; i < 4; ++i) {
            int idx = i * 256 + tid;
            int row = idx >> 3;
            int col = (idx & 7) * 4;
            float4 v = *(const float4*)&Aq[(size_t)(bm + row) * 2048 + kc + col];
            float4 t = {tf32f(v.x), tf32f(v.y), tf32f(v.z), tf32f(v.w)};
            *(float4*)&Qs[row][col] = t;
        }
#pragma unroll
        for (int i = 0; i < 2; ++i) {
            int idx = i * 256 + tid;
            int row = idx >> 3;
            int col = (idx & 7) * 4;
            float4 v = *(const float4*)&Ak[(size_t)(bn + row) * 2048 + kc + col];
            float4 t = {tf32f(v.x), tf32f(v.y), tf32f(v.z), tf32f(v.w)};
            *(float4*)&Ks[row][col] = t;
        }
        __syncthreads();

#pragma unroll
        for (int ks = 0; ks < 4; ++ks) {
            int k8 = ks * 8;
            uint32_t a[2][4];
#pragma unroll
            for (int mi = 0; mi < 2; ++mi) {
                int r = wm * 32 + mi * 16 + g;
                a[mi][0] = __float_as_uint(Qs[r][k8 + tig]);
                a[mi][1] = __float_as_uint(Qs[r + 8][k8 + tig]);
                a[mi][2] = __float_as_uint(Qs[r][k8 + tig + 4]);
                a[mi][3] = __float_as_uint(Qs[r + 8][k8 + tig + 4]);
            }
#pragma unroll
            for (int ni = 0; ni < 4; ++ni) {
                int c = wn * 32 + ni * 8 + g;
                uint32_t b0 = __float_as_uint(Ks[c][k8 + tig]);
                uint32_t b1 = __float_as_uint(Ks[c][k8 + tig + 4]);
#pragma unroll
                for (int mi = 0; mi < 2; ++mi)
                    mma_tf32_16x8x8(acc[mi][ni], a[mi], b0, b1);
            }
        }
        __syncthreads();
    }

    const float sc = 0.125f;
#pragma unroll
    for (int mi = 0; mi < 2; ++mi) {
#pragma unroll
        for (int ni = 0; ni < 4; ++ni) {
            int row = bm + wm * 32 + mi * 16 + g;
            int col = bn + wn * 32 + ni * 8 + 2 * tig;
            __half2 h0 = __floats2half2_rn(__expf(acc[mi][ni][0] * sc),
                                           __expf(acc[mi][ni][1] * sc));
            __half2 h1 = __floats2half2_rn(__expf(acc[mi][ni][2] * sc),
                                           __expf(acc[mi][ni][3] * sc));
            *(__half2*)&Pc[(size_t)row * BHT + col]       = h0;
            *(__half2*)&Pc[(size_t)(row + 8) * BHT + col] = h1;
        }
    }
}

// ===========================================================================
// Kernel 3/5: rd = 1/sum_h p — vectorized: 8 t per thread, uint4 loads.
// ===========================================================================
__global__ void rdenom_kernel(const __half* __restrict__ P,
                              float* __restrict__ RD)
{
    int i8 = blockIdx.x * blockDim.x + threadIdx.x;
    if (i8 >= S_DIM * B_DIM * T_DIM / 8) return;
    int idx = i8 * 8;
    int sb = idx / T_DIM;
    int t  = idx - sb * T_DIM;
    const __half* p = P + (size_t)sb * H_DIM * T_DIM + t;

    float s[8];
#pragma unroll
    for (int i = 0; i < 8; ++i) s[i] = 0.f;
#pragma unroll
    for (int h = 0; h < H_DIM; ++h) {
        uint4 v = *(const uint4*)&p[(size_t)h * T_DIM];
        float2 f0 = __half22float2(*(const __half2*)&v.x);
        float2 f1 = __half22float2(*(const __half2*)&v.y);
        float2 f2 = __half22float2(*(const __half2*)&v.z);
        float2 f3 = __half22float2(*(const __half2*)&v.w);
        s[0] += f0.x; s[1] += f0.y; s[2] += f1.x; s[3] += f1.y;
        s[4] += f2.x; s[5] += f2.y; s[6] += f3.x; s[7] += f3.y;
    }
    float4 r0 = {1.f/s[0], 1.f/s[1], 1.f/s[2], 1.f/s[3]};
    float4 r1 = {1.f/s[4], 1.f/s[5], 1.f/s[6], 1.f/s[7]};
    *(float4*)&RD[idx]     = r0;
    *(float4*)&RD[idx + 4] = r1;
}

// ===========================================================================
// Kernel 4/5: o = (p*rd) @ v via fp16 mma (unchanged).
// ===========================================================================
__global__ __launch_bounds__(256)
void av_mma_kernel(const __half* __restrict__ P,
                   const float* __restrict__ RD,
                   const float* __restrict__ V,
                   float* __restrict__ O)
{
    __shared__ __half As[128][72];
    __shared__ __half Vs[64][70];

    const int bh = blockIdx.y;
    const int b  = bh / H_DIM;
    const int h  = bh % H_DIM;
    const int bm = blockIdx.x * 128;

    const __half* Pb = P  + (size_t)bh * T_DIM;
    const float* RDb = RD + (size_t)b * T_DIM;
    const float* Vb  = V  + (size_t)b * E_DIM + h * D_DIM;
    float*       Ob  = O  + (size_t)b * E_DIM + h * D_DIM;

    const int tid  = threadIdx.x;
    const int wid  = tid >> 5;
    const int lane = tid & 31;
    const int wm = wid >> 1;
    const int wn = wid & 1;
    const int g   = lane >> 2;
    const int tig = lane & 3;

    float acc[2][4][4];
#pragma unroll
    for (int mi = 0; mi < 2; ++mi)
#pragma unroll
        for (int ni = 0; ni < 4; ++ni)
#pragma unroll
            for (int r = 0; r < 4; ++r) acc[mi][ni][r] = 0.f;

    for (int tc = 0; tc < T_DIM; tc += 64) {
#pragma unroll
        for (int i = 0; i < 8; ++i) {
            int idx = i * 256 + tid;
            int row = idx >> 4;
            int c4  = (idx & 15) * 4;
            int s = bm + row;
            uint2  pr = *(const uint2*)&Pb[(size_t)s * BHT + tc + c4];
            float4 r  = *(const float4*)&RDb[(size_t)s * (B_DIM * T_DIM) + tc + c4];
            float2 p01 = __half22float2(*(const __half2*)&pr.x);
            float2 p23 = __half22float2(*(const __half2*)&pr.y);
            *(__half2*)&As[row][c4]     = __floats2half2_rn(p01.x * r.x, p01.y * r.y);
            *(__half2*)&As[row][c4 + 2] = __floats2half2_rn(p23.x * r.z, p23.y * r.w);
        }
#pragma unroll
        for (int i = 0; i < 4; ++i) {
            int idx = i * 256 + tid;
            int t  = idx >> 4;
            int d4 = (idx & 15) * 4;
            float4 v = *(const float4*)&Vb[(size_t)(tc + t) * 2048 + d4];
            Vs[d4 + 0][t] = __float2half_rn(v.x);
            Vs[d4 + 1][t] = __float2half_rn(v.y);
            Vs[d4 + 2][t] = __float2half_rn(v.z);
            Vs[d4 + 3][t] = __float2half_rn(v.w);
        }
        __syncthreads();

#pragma unroll
        for (int ks = 0; ks < 4; ++ks) {
            int k0 = ks * 16;
            uint32_t a[2][4];
#pragma unroll
            for (int mi = 0; mi < 2; ++mi) {
                int r = wm * 32 + mi * 16 + g;
                a[mi][0] = *(const uint32_t*)&As[r][k0 + 2 * tig];
                a[mi][1] = *(const uint32_t*)&As[r + 8][k0 + 2 * tig];
                a[mi][2] = *(const uint32_t*)&As[r][k0 + 2 * tig + 8];
                a[mi][3] = *(const uint32_t*)&As[r + 8][k0 + 2 * tig + 8];
            }
#pragma unroll
            for (int ni = 0; ni < 4; ++ni) {
                int c = wn * 32 + ni * 8 + g;
                uint32_t b0 = *(const uint32_t*)&Vs[c][k0 + 2 * tig];
                uint32_t b1 = *(const uint32_t*)&Vs[c][k0 + 2 * tig + 8];
#pragma unroll
                for (int mi = 0; mi < 2; ++mi)
                    mma_f16_16x8x16(acc[mi][ni], a[mi], b0, b1);
            }
        }
        __syncthreads();
    }

#pragma unroll
    for (int mi = 0; mi < 2; ++mi) {
#pragma unroll
        for (int ni = 0; ni < 4; ++ni) {
            int row = bm + wm * 32 + mi * 16 + g;
            int col = wn * 32 + ni * 8 + 2 * tig;
            float2 o0 = {acc[mi][ni][0], acc[mi][ni][1]};
            float2 o1 = {acc[mi][ni][2], acc[mi][ni][3]};
            *(float2*)&Ob[(size_t)row * 2048 + col]       = o0;
            *(float2*)&Ob[(size_t)(row + 8) * 2048 + col] = o1;
        }
    }
}

// ===========================================================================
// Launch: qkv(3xTF32) -> scores(mma) -> rdenom -> av(mma) -> out(3xTF32)
// ===========================================================================
extern "C" void kernel_launch(void* const* d_in, const int* in_sizes, int n_in,
                              void* d_out, int out_size)
{
    (void)in_sizes; (void)n_in; (void)out_size;
    const float* x  = (const float*)d_in[0];
    const float* Wq = (const float*)d_in[1];
    const float* bq = (const float*)d_in[2];
    const float* Wk = (const float*)d_in[3];
    const float* bk = (const float*)d_in[4];
    const float* Wv = (const float*)d_in[5];
    const float* bv = (const float*)d_in[6];
    const float* Wo = (const float*)d_in[7];
    const float* bo = (const float*)d_in[8];
    float* out = (float*)d_out;

    float *q, *k, *v, *o, *rd;
    __half* p;
    cudaGetSymbolAddress((void**)&q,  g_q);
    cudaGetSymbolAddress((void**)&k,  g_k);
    cudaGetSymbolAddress((void**)&v,  g_v);
    cudaGetSymbolAddress((void**)&o,  g_o);
    cudaGetSymbolAddress((void**)&p,  g_p);
    cudaGetSymbolAddress((void**)&rd, g_rd);

    dim3 gQKV(E_DIM / 64, M_DIM / 128, 3);                 // (16, 32, 3)
    qkv_proj_kernel<<<gQKV, 256>>>(x, Wq, bq, Wk, bk, Wv, bv, q, k, v);

    dim3 gScore(T_DIM / 64, S_DIM / 128, B_DIM * H_DIM);   // (32, 16, 32)
    scores_mma_kernel<<<gScore, 256>>>(q, k, p);

    int nRd = S_DIM * B_DIM * T_DIM / 8;
    rdenom_kernel<<<(nRd + 255) / 256, 256>>>(p, rd);

    dim3 gAV(S_DIM / 128, B_DIM * H_DIM);                  // (16, 32)
    av_mma_kernel<<<gAV, 256>>>(p, rd, v, o);

    dim3 gProj(E_DIM / 64, M_DIM / 128);                   // (16, 32)
    out_proj_kernel<<<gProj, 256>>>(o, Wo, bo, out);
}

// round 12
// speedup vs baseline: 1.1650x; 1.1650x over previous
#include <cuda_runtime.h>
#include <cuda_fp16.h>
#include <cstdint>

// Problem dims (fixed by the dataset)
#define S_DIM 2048
#define B_DIM 2
#define E_DIM 1024
#define H_DIM 16
#define D_DIM 64
#define T_DIM 2048
#define M_DIM (S_DIM * B_DIM)          // 4096 rows of the flattened (s,b) axis
#define BHT   (B_DIM * H_DIM * T_DIM)  // 65536: stride of s in the scores tensor

// -------- static scratch (allocation-free rule: __device__ globals) --------
__device__ float  g_q[M_DIM * E_DIM];                         // 16 MB
__device__ float  g_k[M_DIM * E_DIM];                         // 16 MB
__device__ float  g_v[M_DIM * E_DIM];                         // 16 MB
__device__ float  g_o[M_DIM * E_DIM];                         // 16 MB
__device__ __half g_p[(size_t)S_DIM * B_DIM * H_DIM * T_DIM]; // 256 MiB: exp(scores), fp16
__device__ float  g_rd[S_DIM * B_DIM * T_DIM];                // 32 MB: 1/sum_h

// ---------------- mma wrappers ----------------
__device__ __forceinline__ uint32_t f2tf32(float x) {
    uint32_t r;
    asm("cvt.rna.tf32.f32 %0, %1;" : "=r"(r) : "f"(x));
    return r;
}
__device__ __forceinline__ float tf32f(float x) {
    return __uint_as_float(f2tf32(x));
}

__device__ __forceinline__
void mma_tf32_16x8x8(float c[4], const uint32_t a[4], uint32_t b0, uint32_t b1) {
    asm volatile(
        "mma.sync.aligned.m16n8k8.row.col.f32.tf32.tf32.f32 "
        "{%0,%1,%2,%3}, {%4,%5,%6,%7}, {%8,%9}, {%0,%1,%2,%3};"
        : "+f"(c[0]), "+f"(c[1]), "+f"(c[2]), "+f"(c[3])
        : "r"(a[0]), "r"(a[1]), "r"(a[2]), "r"(a[3]), "r"(b0), "r"(b1));
}

__device__ __forceinline__
void mma_f16_16x8x16(float c[4], const uint32_t a[4], uint32_t b0, uint32_t b1) {
    asm volatile(
        "mma.sync.aligned.m16n8k16.row.col.f32.f16.f16.f32 "
        "{%0,%1,%2,%3}, {%4,%5,%6,%7}, {%8,%9}, {%0,%1,%2,%3};"
        : "+f"(c[0]), "+f"(c[1]), "+f"(c[2]), "+f"(c[3])
        : "r"(a[0]), "r"(a[1]), "r"(a[2]), "r"(a[3]), "r"(b0), "r"(b1));
}

// ===========================================================================
// Core NT-GEMM tile body (fp32 SIMT, R5-proven): C = A * W^T + bias, 128x128.
// A: M x K row-major, W: N x K row-major. Register-prefetch pipelined.
// ===========================================================================
__device__ __forceinline__
void gemm_nt_tile(const float* __restrict__ A,
                  const float* __restrict__ W,
                  const float* __restrict__ bias,
                  float* __restrict__ C,
                  int K, int N, int bm, int bn)
{
    __shared__ float Ast[16][132];
    __shared__ float Bst[16][132];

    const int tid = threadIdx.x;
    const int tx = tid & 15;
    const int ty = tid >> 4;

    const int l_row0 = tid >> 2;
    const int l_row1 = (256 + tid) >> 2;
    const int l_k4   = (tid & 3) * 4;

    float acc[8][8];
#pragma unroll
    for (int i = 0; i < 8; ++i)
#pragma unroll
        for (int j = 0; j < 8; ++j) acc[i][j] = 0.f;

    float4 pa0, pa1, pb0, pb1;
    pa0 = *(const float4*)&A[(size_t)(bm + l_row0) * K + l_k4];
    pa1 = *(const float4*)&A[(size_t)(bm + l_row1) * K + l_k4];
    pb0 = *(const float4*)&W[(size_t)(bn + l_row0) * K + l_k4];
    pb1 = *(const float4*)&W[(size_t)(bn + l_row1) * K + l_k4];

    for (int kt = 0; kt < K; kt += 16) {
        Ast[l_k4 + 0][l_row0] = pa0.x;  Ast[l_k4 + 1][l_row0] = pa0.y;
        Ast[l_k4 + 2][l_row0] = pa0.z;  Ast[l_k4 + 3][l_row0] = pa0.w;
        Ast[l_k4 + 0][l_row1] = pa1.x;  Ast[l_k4 + 1][l_row1] = pa1.y;
        Ast[l_k4 + 2][l_row1] = pa1.z;  Ast[l_k4 + 3][l_row1] = pa1.w;
        Bst[l_k4 + 0][l_row0] = pb0.x;  Bst[l_k4 + 1][l_row0] = pb0.y;
        Bst[l_k4 + 2][l_row0] = pb0.z;  Bst[l_k4 + 3][l_row0] = pb0.w;
        Bst[l_k4 + 0][l_row1] = pb1.x;  Bst[l_k4 + 1][l_row1] = pb1.y;
        Bst[l_k4 + 2][l_row1] = pb1.z;  Bst[l_k4 + 3][l_row1] = pb1.w;
        __syncthreads();

        if (kt + 16 < K) {
            int kn = kt + 16;
            pa0 = *(const float4*)&A[(size_t)(bm + l_row0) * K + kn + l_k4];
            pa1 = *(const float4*)&A[(size_t)(bm + l_row1) * K + kn + l_k4];
            pb0 = *(const float4*)&W[(size_t)(bn + l_row0) * K + kn + l_k4];
            pb1 = *(const float4*)&W[(size_t)(bn + l_row1) * K + kn + l_k4];
        }

#pragma unroll
        for (int kk = 0; kk < 16; ++kk) {
            float4 a0 = *(const float4*)&Ast[kk][ty * 4];
            float4 a1 = *(const float4*)&Ast[kk][64 + ty * 4];
            float4 b0 = *(const float4*)&Bst[kk][tx * 4];
            float4 b1 = *(const float4*)&Bst[kk][64 + tx * 4];
            float av[8] = {a0.x, a0.y, a0.z, a0.w, a1.x, a1.y, a1.z, a1.w};
            float bv[8] = {b0.x, b0.y, b0.z, b0.w, b1.x, b1.y, b1.z, b1.w};
#pragma unroll
            for (int i = 0; i < 8; ++i)
#pragma unroll
                for (int j = 0; j < 8; ++j) acc[i][j] += av[i] * bv[j];
        }
        __syncthreads();
    }

    float4 bs0 = *(const float4*)&bias[bn + tx * 4];
    float4 bs1 = *(const float4*)&bias[bn + 64 + tx * 4];
#pragma unroll
    for (int i = 0; i < 8; ++i) {
        int row = bm + ((i < 4) ? (ty * 4 + i) : (64 + ty * 4 + (i - 4)));
        float4 o0 = {acc[i][0] + bs0.x, acc[i][1] + bs0.y,
                     acc[i][2] + bs0.z, acc[i][3] + bs0.w};
        float4 o1 = {acc[i][4] + bs1.x, acc[i][5] + bs1.y,
                     acc[i][6] + bs1.z, acc[i][7] + bs1.w};
        *(float4*)&C[(size_t)row * N + bn + tx * 4]      = o0;
        *(float4*)&C[(size_t)row * N + bn + 64 + tx * 4] = o1;
    }
}

// Kernel 1/5: fused Q/K/V projections (blockIdx.z selects the triple)
__global__ __launch_bounds__(256, 2)
void qkv_proj_kernel(const float* __restrict__ x,
                     const float* __restrict__ Wq, const float* __restrict__ bq,
                     const float* __restrict__ Wk, const float* __restrict__ bk,
                     const float* __restrict__ Wv, const float* __restrict__ bv,
                     float* __restrict__ q, float* __restrict__ k,
                     float* __restrict__ v)
{
    const float* W; const float* bias; float* C;
    if (blockIdx.z == 0)      { W = Wq; bias = bq; C = q; }
    else if (blockIdx.z == 1) { W = Wk; bias = bk; C = k; }
    else                      { W = Wv; bias = bv; C = v; }
    gemm_nt_tile(x, W, bias, C, E_DIM, E_DIM,
                 blockIdx.y * 128, blockIdx.x * 128);
}

// Kernel 5/5: output projection
__global__ __launch_bounds__(256, 2)
void out_proj_kernel(const float* __restrict__ o,
                     const float* __restrict__ Wo, const float* __restrict__ bo,
                     float* __restrict__ out)
{
    gemm_nt_tile(o, Wo, bo, out, E_DIM, E_DIM,
                 blockIdx.y * 128, blockIdx.x * 128);
}

// ===========================================================================
// Kernel 2/5: p[s,b,h,t] = exp((q.k)/8) via tf32 mma.m16n8k8 (R5-proven).
// ===========================================================================
__global__ __launch_bounds__(256)
void scores_mma_kernel(const float* __restrict__ Q,
                       const float* __restrict__ Kv,
                       __half* __restrict__ P)
{
    __shared__ float Qs[128][36];
    __shared__ float Ks[64][36];

    const int bh = blockIdx.z;
    const int b  = bh / H_DIM;
    const int h  = bh % H_DIM;
    const float* Aq = Q  + (size_t)b * E_DIM + h * D_DIM;
    const float* Ak = Kv + (size_t)b * E_DIM + h * D_DIM;
    __half* Pc = P + (size_t)bh * T_DIM;

    const int bm = blockIdx.y * 128;
    const int bn = blockIdx.x * 64;
    const int tid  = threadIdx.x;
    const int wid  = tid >> 5;
    const int lane = tid & 31;
    const int wm = wid >> 1;
    const int wn = wid & 1;
    const int g   = lane >> 2;
    const int tig = lane & 3;

    float acc[2][4][4];
#pragma unroll
    for (int mi = 0; mi < 2; ++mi)
#pragma unroll
        for (int ni = 0; ni < 4; ++ni)
#pragma unroll
            for (int r = 0; r < 4; ++r) acc[mi][ni][r] = 0.f;

#pragma unroll
    for (int kc = 0; kc < D_DIM; kc += 32) {
#pragma unroll
        for (int i = 0; i < 4; ++i) {
            int idx = i * 256 + tid;
            int row = idx >> 3;
            int col = (idx & 7) * 4;
            float4 v = *(const float4*)&Aq[(size_t)(bm + row) * 2048 + kc + col];
            float4 t = {tf32f(v.x), tf32f(v.y), tf32f(v.z), tf32f(v.w)};
            *(float4*)&Qs[row][col] = t;
        }
#pragma unroll
        for (int i = 0; i < 2; ++i) {
            int idx = i * 256 + tid;
            int row = idx >> 3;
            int col = (idx & 7) * 4;
            float4 v = *(const float4*)&Ak[(size_t)(bn + row) * 2048 + kc + col];
            float4 t = {tf32f(v.x), tf32f(v.y), tf32f(v.z), tf32f(v.w)};
            *(float4*)&Ks[row][col] = t;
        }
        __syncthreads();

#pragma unroll
        for (int ks = 0; ks < 4; ++ks) {
            int k8 = ks * 8;
            uint32_t a[2][4];
#pragma unroll
            for (int mi = 0; mi < 2; ++mi) {
                int r = wm * 32 + mi * 16 + g;
                a[mi][0] = __float_as_uint(Qs[r][k8 + tig]);
                a[mi][1] = __float_as_uint(Qs[r + 8][k8 + tig]);
                a[mi][2] = __float_as_uint(Qs[r][k8 + tig + 4]);
                a[mi][3] = __float_as_uint(Qs[r + 8][k8 + tig + 4]);
            }
#pragma unroll
            for (int ni = 0; ni < 4; ++ni) {
                int c = wn * 32 + ni * 8 + g;
                uint32_t b0 = __float_as_uint(Ks[c][k8 + tig]);
                uint32_t b1 = __float_as_uint(Ks[c][k8 + tig + 4]);
#pragma unroll
                for (int mi = 0; mi < 2; ++mi)
                    mma_tf32_16x8x8(acc[mi][ni], a[mi], b0, b1);
            }
        }
        __syncthreads();
    }

    const float sc = 0.125f;
#pragma unroll
    for (int mi = 0; mi < 2; ++mi) {
#pragma unroll
        for (int ni = 0; ni < 4; ++ni) {
            int row = bm + wm * 32 + mi * 16 + g;
            int col = bn + wn * 32 + ni * 8 + 2 * tig;
            __half2 h0 = __floats2half2_rn(__expf(acc[mi][ni][0] * sc),
                                           __expf(acc[mi][ni][1] * sc));
            __half2 h1 = __floats2half2_rn(__expf(acc[mi][ni][2] * sc),
                                           __expf(acc[mi][ni][3] * sc));
            *(__half2*)&Pc[(size_t)row * BHT + col]       = h0;
            *(__half2*)&Pc[(size_t)(row + 8) * BHT + col] = h1;
        }
    }
}

// ===========================================================================
// Kernel 3/5: rd = 1/sum_h p — vectorized: 8 t per thread, uint4 loads.
// ===========================================================================
__global__ void rdenom_kernel(const __half* __restrict__ P,
                              float* __restrict__ RD)
{
    int i8 = blockIdx.x * blockDim.x + threadIdx.x;
    if (i8 >= S_DIM * B_DIM * T_DIM / 8) return;
    int idx = i8 * 8;
    int sb = idx / T_DIM;
    int t  = idx - sb * T_DIM;
    const __half* p = P + (size_t)sb * H_DIM * T_DIM + t;

    float s[8];
#pragma unroll
    for (int i = 0; i < 8; ++i) s[i] = 0.f;
#pragma unroll
    for (int h = 0; h < H_DIM; ++h) {
        uint4 v = *(const uint4*)&p[(size_t)h * T_DIM];
        float2 f0 = __half22float2(*(const __half2*)&v.x);
        float2 f1 = __half22float2(*(const __half2*)&v.y);
        float2 f2 = __half22float2(*(const __half2*)&v.z);
        float2 f3 = __half22float2(*(const __half2*)&v.w);
        s[0] += f0.x; s[1] += f0.y; s[2] += f1.x; s[3] += f1.y;
        s[4] += f2.x; s[5] += f2.y; s[6] += f3.x; s[7] += f3.y;
    }
    float4 r0 = {1.f/s[0], 1.f/s[1], 1.f/s[2], 1.f/s[3]};
    float4 r1 = {1.f/s[4], 1.f/s[5], 1.f/s[6], 1.f/s[7]};
    *(float4*)&RD[idx]     = r0;
    *(float4*)&RD[idx + 4] = r1;
}

// ===========================================================================
// Kernel 4/5: o = (p*rd) @ v via fp16 mma (R5-proven).
// ===========================================================================
__global__ __launch_bounds__(256)
void av_mma_kernel(const __half* __restrict__ P,
                   const float* __restrict__ RD,
                   const float* __restrict__ V,
                   float* __restrict__ O)
{
    __shared__ __half As[128][72];
    __shared__ __half Vs[64][70];

    const int bh = blockIdx.y;
    const int b  = bh / H_DIM;
    const int h  = bh % H_DIM;
    const int bm = blockIdx.x * 128;

    const __half* Pb = P  + (size_t)bh * T_DIM;
    const float* RDb = RD + (size_t)b * T_DIM;
    const float* Vb  = V  + (size_t)b * E_DIM + h * D_DIM;
    float*       Ob  = O  + (size_t)b * E_DIM + h * D_DIM;

    const int tid  = threadIdx.x;
    const int wid  = tid >> 5;
    const int lane = tid & 31;
    const int wm = wid >> 1;
    const int wn = wid & 1;
    const int g   = lane >> 2;
    const int tig = lane & 3;

    float acc[2][4][4];
#pragma unroll
    for (int mi = 0; mi < 2; ++mi)
#pragma unroll
        for (int ni = 0; ni < 4; ++ni)
#pragma unroll
            for (int r = 0; r < 4; ++r) acc[mi][ni][r] = 0.f;

    for (int tc = 0; tc < T_DIM; tc += 64) {
#pragma unroll
        for (int i = 0; i < 8; ++i) {
            int idx = i * 256 + tid;
            int row = idx >> 4;
            int c4  = (idx & 15) * 4;
            int s = bm + row;
            uint2  pr = *(const uint2*)&Pb[(size_t)s * BHT + tc + c4];
            float4 r  = *(const float4*)&RDb[(size_t)s * (B_DIM * T_DIM) + tc + c4];
            float2 p01 = __half22float2(*(const __half2*)&pr.x);
            float2 p23 = __half22float2(*(const __half2*)&pr.y);
            *(__half2*)&As[row][c4]     = __floats2half2_rn(p01.x * r.x, p01.y * r.y);
            *(__half2*)&As[row][c4 + 2] = __floats2half2_rn(p23.x * r.z, p23.y * r.w);
        }
#pragma unroll
        for (int i = 0; i < 4; ++i) {
            int idx = i * 256 + tid;
            int t  = idx >> 4;
            int d4 = (idx & 15) * 4;
            float4 v = *(const float4*)&Vb[(size_t)(tc + t) * 2048 + d4];
            Vs[d4 + 0][t] = __float2half_rn(v.x);
            Vs[d4 + 1][t] = __float2half_rn(v.y);
            Vs[d4 + 2][t] = __float2half_rn(v.z);
            Vs[d4 + 3][t] = __float2half_rn(v.w);
        }
        __syncthreads();

#pragma unroll
        for (int ks = 0; ks < 4; ++ks) {
            int k0 = ks * 16;
            uint32_t a[2][4];
#pragma unroll
            for (int mi = 0; mi < 2; ++mi) {
                int r = wm * 32 + mi * 16 + g;
                a[mi][0] = *(const uint32_t*)&As[r][k0 + 2 * tig];
                a[mi][1] = *(const uint32_t*)&As[r + 8][k0 + 2 * tig];
                a[mi][2] = *(const uint32_t*)&As[r][k0 + 2 * tig + 8];
                a[mi][3] = *(const uint32_t*)&As[r + 8][k0 + 2 * tig + 8];
            }
#pragma unroll
            for (int ni = 0; ni < 4; ++ni) {
                int c = wn * 32 + ni * 8 + g;
                uint32_t b0 = *(const uint32_t*)&Vs[c][k0 + 2 * tig];
                uint32_t b1 = *(const uint32_t*)&Vs[c][k0 + 2 * tig + 8];
#pragma unroll
                for (int mi = 0; mi < 2; ++mi)
                    mma_f16_16x8x16(acc[mi][ni], a[mi], b0, b1);
            }
        }
        __syncthreads();
    }

#pragma unroll
    for (int mi = 0; mi < 2; ++mi) {
#pragma unroll
        for (int ni = 0; ni < 4; ++ni) {
            int row = bm + wm * 32 + mi * 16 + g;
            int col = wn * 32 + ni * 8 + 2 * tig;
            float2 o0 = {acc[mi][ni][0], acc[mi][ni][1]};
            float2 o1 = {acc[mi][ni][2], acc[mi][ni][3]};
            *(float2*)&Ob[(size_t)row * 2048 + col]       = o0;
            *(float2*)&Ob[(size_t)(row + 8) * 2048 + col] = o1;
        }
    }
}

// ===========================================================================
// Launch: qkv(fp32 SIMT) -> scores(mma) -> rdenom(vec) -> av(mma) -> out
// ===========================================================================
extern "C" void kernel_launch(void* const* d_in, const int* in_sizes, int n_in,
                              void* d_out, int out_size)
{
    (void)in_sizes; (void)n_in; (void)out_size;
    const float* x  = (const float*)d_in[0];
    const float* Wq = (const float*)d_in[1];
    const float* bq = (const float*)d_in[2];
    const float* Wk = (const float*)d_in[3];
    const float* bk = (const float*)d_in[4];
    const float* Wv = (const float*)d_in[5];
    const float* bv = (const float*)d_in[6];
    const float* Wo = (const float*)d_in[7];
    const float* bo = (const float*)d_in[8];
    float* out = (float*)d_out;

    float *q, *k, *v, *o, *rd;
    __half* p;
    cudaGetSymbolAddress((void**)&q,  g_q);
    cudaGetSymbolAddress((void**)&k,  g_k);
    cudaGetSymbolAddress((void**)&v,  g_v);
    cudaGetSymbolAddress((void**)&o,  g_o);
    cudaGetSymbolAddress((void**)&p,  g_p);
    cudaGetSymbolAddress((void**)&rd, g_rd);

    dim3 gQKV(E_DIM / 128, M_DIM / 128, 3);                // (8, 32, 3)
    qkv_proj_kernel<<<gQKV, 256>>>(x, Wq, bq, Wk, bk, Wv, bv, q, k, v);

    dim3 gScore(T_DIM / 64, S_DIM / 128, B_DIM * H_DIM);   // (32, 16, 32)
    scores_mma_kernel<<<gScore, 256>>>(q, k, p);

    int nRd = S_DIM * B_DIM * T_DIM / 8;
    rdenom_kernel<<<(nRd + 255) / 256, 256>>>(p, rd);

    dim3 gAV(S_DIM / 128, B_DIM * H_DIM);                  // (16, 32)
    av_mma_kernel<<<gAV, 256>>>(p, rd, v, o);

    dim3 gProj(E_DIM / 128, M_DIM / 128);                  // (8, 32)
    out_proj_kernel<<<gProj, 256>>>(o, Wo, bo, out);
}